// round 11
// baseline (speedup 1.0000x reference)
#include <cuda_runtime.h>

// Problem constants (fixed by the reference)
#define BSZ    2
#define LEN    2048
#define DQ     512
#define SQ     4
#define SH     2                 // s-lanes per thread (K1 and K3)
#define NC     128               // fine chunks along L (all kernels)
#define CHUNKF (LEN / NC)        // 16 steps per fine chunk
#define NCL    (NC / 32)         // fine chunks per lane in K2 warp scan (4)
#define EPSQ   1e-6f

typedef unsigned long long u64;

// Scratch: chunk summaries and carries, laid out [b][chunk][s][d].
// float4 layout == {lo:(x,y), hi:(z,w)} as 2x u64 — K1/K3 access packed,
// K2 accesses as float4. Identical memory layout.
__device__ float4 g_Q  [BSZ * NC * SQ * DQ];
__device__ float4 g_H  [BSZ * NC * SQ * DQ];
__device__ float4 g_Hin[BSZ * NC * SQ * DQ];

// ---------------------------------------------------------------------------
// f32x2 packed primitives (FFMA2 path — ptxas never emits these from C++)
// ---------------------------------------------------------------------------
__device__ __forceinline__ u64 pk(float lo, float hi) {
    u64 r; asm("mov.b64 %0, {%1, %2};" : "=l"(r) : "f"(lo), "f"(hi)); return r;
}
__device__ __forceinline__ void upk(float& lo, float& hi, u64 v) {
    asm("mov.b64 {%0, %1}, %2;" : "=f"(lo), "=f"(hi) : "l"(v));
}
__device__ __forceinline__ u64 fma2(u64 a, u64 b, u64 c) {
    u64 r; asm("fma.rn.f32x2 %0, %1, %2, %3;" : "=l"(r) : "l"(a), "l"(b), "l"(c)); return r;
}
__device__ __forceinline__ u64 add2(u64 a, u64 b) {
    u64 r; asm("add.rn.f32x2 %0, %1, %2;" : "=l"(r) : "l"(a), "l"(b)); return r;
}
__device__ __forceinline__ float fneg(float x) {
    return __int_as_float(__float_as_int(x) ^ 0x80000000);
}

// Packed quaternion: lo=(x,y), hi=(z,w)
struct PQ { u64 lo, hi; };

// Left-operand permutation set for r = a (x) X (X splatted per component):
//   rlo = Xx*(ax,ay) + Xy*(-ay,ax) + Xz*(-az,-aw) + Xw*(-aw,az)
//   rhi = Xx*(az,aw) + Xy*(aw,-az) + Xz*( ax, ay) + Xw*(-ay,ax)
// Note rhi reuses m0l (term3) and m1l (term4).
struct QP { u64 m0l, m0h, m1l, m1h, m2l, m3l; };

__device__ __forceinline__ QP make_perm(float ax, float ay, float az, float aw) {
    QP p;
    const float nay = fneg(ay), naz = fneg(az), naw = fneg(aw);
    p.m0l = pk(ax, ay);   p.m0h = pk(az, aw);
    p.m1l = pk(nay, ax);  p.m1h = pk(aw, naz);
    p.m2l = pk(naz, naw); p.m3l = pk(naw, az);
    return p;
}

// r = a (x) X + c   (X given as component splats, c packed; 8 FFMA2)
__device__ __forceinline__ PQ qmac(const QP& a, u64 sx, u64 sy, u64 sz, u64 sw,
                                   u64 clo, u64 chi) {
    PQ r;
    r.lo = fma2(sx, a.m0l, fma2(sy, a.m1l, fma2(sz, a.m2l, fma2(sw, a.m3l, clo))));
    r.hi = fma2(sx, a.m0h, fma2(sy, a.m1h, fma2(sz, a.m0l, fma2(sw, a.m1l, chi))));
    return r;
}

// Splats of a packed quaternion (unpack + 4 packs)
__device__ __forceinline__ void splat4(const PQ v, u64& sx, u64& sy, u64& sz, u64& sw) {
    float x, y, z, w;
    upk(x, y, v.lo); upk(z, w, v.hi);
    sx = pk(x, x); sy = pk(y, y); sz = pk(z, z); sw = pk(w, w);
}

// Approximate reciprocal (no Newton step): rel err ~2.4e-7, fine vs 1e-3 tol.
__device__ __forceinline__ float frcp(float x) {
    float r; asm("rcp.approx.f32 %0, %1;" : "=f"(r) : "f"(x)); return r;
}

// Per-step transition quaternion scalars (ah = 0.5*A):
__device__ __forceinline__ void step_q_s(const float dtv, const float4 ah,
                                         float& qx, float& qy, float& qz, float& qw) {
    const float wr = dtv * ah.x, wi = dtv * ah.y, wj = dtv * ah.z, wk = dtv * ah.w;
    const float omr = 1.0f - wr;
    const float vve = fmaf(wi, wi, fmaf(wj, wj, fmaf(wk, wk, EPSQ)));
    const float n2  = fmaf(omr, omr, vve);
    const float r2  = frcp(n2) * 2.0f;
    qx = fmaf(omr, r2, -1.0f); qy = wi * r2; qz = wj * r2; qw = wk * r2;
}

// Scalar float4 quaternion helpers (K2 only)
__device__ __forceinline__ float4 qmuladd(const float4 a, const float4 b, const float4 c) {
    float4 r;
    r.x = fmaf(a.x, b.x, fmaf(-a.y, b.y, fmaf(-a.z, b.z, fmaf(-a.w, b.w, c.x))));
    r.y = fmaf(a.x, b.y, fmaf( a.y, b.x, fmaf( a.z, b.w, fmaf(-a.w, b.z, c.y))));
    r.z = fmaf(a.x, b.z, fmaf(-a.y, b.w, fmaf( a.z, b.x, fmaf( a.w, b.y, c.z))));
    r.w = fmaf(a.x, b.w, fmaf( a.y, b.z, fmaf(-a.z, b.y, fmaf( a.w, b.x, c.w))));
    return r;
}
__device__ __forceinline__ float4 qmul(const float4 a, const float4 b) {
    return qmuladd(a, b, make_float4(0.f, 0.f, 0.f, 0.f));
}
__device__ __forceinline__ float4 shfl_up4(const float4 v, int off) {
    float4 r;
    r.x = __shfl_up_sync(0xffffffffu, v.x, off);
    r.y = __shfl_up_sync(0xffffffffu, v.y, off);
    r.z = __shfl_up_sync(0xffffffffu, v.z, off);
    r.w = __shfl_up_sync(0xffffffffu, v.w, off);
    return r;
}

// SH=2 thread decomposition: lane bits [0:4)=d_low4, bit4=s-half, d_hi, c, b.
struct DeH { int b, c, d, s0, hbit; };
__device__ __forceinline__ DeH decompH(int gt) {
    DeH r;
    const int lane16 = gt & 15;
    r.hbit = (gt >> 4) & 1;
    const int rest = gt >> 5;
    r.d = ((rest & 31) << 4) + lane16;
    r.c = (rest >> 5) & (NC - 1);
    r.b = rest >> 12;
    r.s0 = r.hbit * SH;
    return r;
}

// ---------------------------------------------------------------------------
// K1: per-(b, chunk, d, s-half) thread — chunk transforms (Q, H), FFMA2 path.
// ---------------------------------------------------------------------------
__global__ void __launch_bounds__(256, 4)
k_summary(const float* __restrict__ u, const float* __restrict__ dt,
          const float* __restrict__ Bin,
          const float* __restrict__ A_log, const float* __restrict__ A_i,
          const float* __restrict__ A_j,  const float* __restrict__ A_k)
{
    const DeH de = decompH(blockIdx.x * blockDim.x + threadIdx.x);
    const int d = de.d, c = de.c, b = de.b, s0 = de.s0;

    float4 ah[SH];
#pragma unroll
    for (int s = 0; s < SH; s++) {
        const int ai = d * SQ + s0 + s;
        ah[s] = make_float4(-0.5f * __expf(A_log[ai]), 0.5f * A_i[ai],
                             0.5f * A_j[ai],           0.5f * A_k[ai]);
    }

    const float4* __restrict__ u4 = (const float4*)u;
    const float4* __restrict__ B4 = (const float4*)Bin;

    const int t0 = c * CHUNKF;
    PQ Qp[SH], Hp[SH];

    for (int i = 0; i < CHUNKF; i++) {
        const int td = b * LEN + t0 + i;
        const float  dtv = dt[td * DQ + d];
        const float4 uu  = u4[td * DQ + d];
        const float  hdt = 0.5f * dtv;
        // us splats (shared across s)
        const u64 sux = pk(uu.x * hdt, uu.x * hdt);
        const u64 suy = pk(uu.y * hdt, uu.y * hdt);
        const u64 suz = pk(uu.z * hdt, uu.z * hdt);
        const u64 suw = pk(uu.w * hdt, uu.w * hdt);
#pragma unroll
        for (int s = 0; s < SH; s++) {
            const float4 Bq = B4[td * SQ + s0 + s];
            const QP bp = make_perm(Bq.x, Bq.y, Bq.z, Bq.w);
            const PQ Bu0 = qmac(bp, sux, suy, suz, suw, 0ull, 0ull);

            float qx, qy, qz, qw;
            step_q_s(dtv, ah[s], qx, qy, qz, qw);
            const QP qp = make_perm(qx, qy, qz, qw);

            if (i == 0) {
                // H = q (x) Bu0 + Bu0 ; Q = q
                u64 sx, sy, sz, sw; splat4(Bu0, sx, sy, sz, sw);
                Hp[s] = qmac(qp, sx, sy, sz, sw, Bu0.lo, Bu0.hi);
                Qp[s].lo = pk(qx, qy); Qp[s].hi = pk(qz, qw);
            } else {
                // H = q (x) (H + Bu0) + Bu0
                PQ X; X.lo = add2(Hp[s].lo, Bu0.lo); X.hi = add2(Hp[s].hi, Bu0.hi);
                u64 sx, sy, sz, sw; splat4(X, sx, sy, sz, sw);
                Hp[s] = qmac(qp, sx, sy, sz, sw, Bu0.lo, Bu0.hi);
                // Q = q (x) Q
                u64 gx, gy, gz, gw; splat4(Qp[s], gx, gy, gz, gw);
                Qp[s] = qmac(qp, gx, gy, gz, gw, 0ull, 0ull);
            }
        }
    }

#pragma unroll
    for (int s = 0; s < SH; s++) {
        const int idx = ((b * NC + c) * SQ + s0 + s) * DQ + d;
        ((ulonglong2*)g_Q)[idx] = make_ulonglong2(Qp[s].lo, Qp[s].hi);
        ((ulonglong2*)g_H)[idx] = make_ulonglong2(Hp[s].lo, Hp[s].hi);
    }
}

// ---------------------------------------------------------------------------
// K2: warp-parallel affine scan (scalar float4; ~3us, unchanged from R8).
// ---------------------------------------------------------------------------
__global__ void __launch_bounds__(256)
k_carry()
{
    const int gt = blockIdx.x * blockDim.x + threadIdx.x;
    const int lane = gt & 31;
    const int w = gt >> 5;                 // chain id in [0, BSZ*SQ*DQ)
    const int d = w & (DQ - 1);
    const int s = (w >> 9) & (SQ - 1);
    const int b = w >> 11;

    const int cstride = SQ * DQ;
    const int base = (b * NC * SQ + s) * DQ + d;
    const int c0 = lane * NCL;

    float4 Qc[NCL], Hc[NCL];
#pragma unroll
    for (int j = 0; j < NCL; j++) {
        const int idx = base + (c0 + j) * cstride;
        Qc[j] = g_Q[idx];
        Hc[j] = g_H[idx];
    }

    float4 Qs = Qc[0], Hs = Hc[0];
#pragma unroll
    for (int j = 1; j < NCL; j++) {
        Hs = qmuladd(Qc[j], Hs, Hc[j]);
        Qs = qmul(Qc[j], Qs);
    }

#pragma unroll
    for (int off = 1; off < 32; off <<= 1) {
        const float4 Qp = shfl_up4(Qs, off);
        const float4 Hp = shfl_up4(Hs, off);
        if (lane >= off) {
            Hs = qmuladd(Qs, Hp, Hs);
            Qs = qmul(Qs, Qp);
        }
    }

    float4 h = shfl_up4(Hs, 1);
    if (lane == 0) h = make_float4(0.f, 0.f, 0.f, 0.f);

#pragma unroll
    for (int j = 0; j < NCL; j++) {
        const int idx = base + (c0 + j) * cstride;
        g_Hin[idx] = h;
        h = qmuladd(Qc[j], h, Hc[j]);
    }
}

// ---------------------------------------------------------------------------
// K3: per-(b, chunk, d, s-half) thread — recompute with carry, FFMA2 path.
//     Pair-reduce y (packed) across s-halves via shfl_xor(16) on u64.
// ---------------------------------------------------------------------------
__global__ void __launch_bounds__(256, 4)
k_final(const float* __restrict__ u, const float* __restrict__ dt,
        const float* __restrict__ Bin, const float* __restrict__ Cin,
        const float* __restrict__ A_log, const float* __restrict__ A_i,
        const float* __restrict__ A_j,  const float* __restrict__ A_k,
        float* __restrict__ out)
{
    const DeH de = decompH(blockIdx.x * blockDim.x + threadIdx.x);
    const int d = de.d, c = de.c, b = de.b, s0 = de.s0;

    float4 ah[SH];
#pragma unroll
    for (int s = 0; s < SH; s++) {
        const int ai = d * SQ + s0 + s;
        ah[s] = make_float4(-0.5f * __expf(A_log[ai]), 0.5f * A_i[ai],
                             0.5f * A_j[ai],           0.5f * A_k[ai]);
    }

    PQ h[SH];
#pragma unroll
    for (int s = 0; s < SH; s++) {
        const ulonglong2 hv = ((const ulonglong2*)g_Hin)[((b * NC + c) * SQ + s0 + s) * DQ + d];
        h[s].lo = hv.x; h[s].hi = hv.y;
    }

    const float4* __restrict__ u4 = (const float4*)u;
    const float4* __restrict__ B4 = (const float4*)Bin;
    const float4* __restrict__ C4 = (const float4*)Cin;
    ulonglong2* __restrict__ o2 = (ulonglong2*)out;

    const int t0 = c * CHUNKF;
    for (int i = 0; i < CHUNKF; i++) {
        const int td = b * LEN + t0 + i;
        const float  dtv = dt[td * DQ + d];
        const float4 uu  = u4[td * DQ + d];
        const float  hdt = 0.5f * dtv;
        const u64 sux = pk(uu.x * hdt, uu.x * hdt);
        const u64 suy = pk(uu.y * hdt, uu.y * hdt);
        const u64 suz = pk(uu.z * hdt, uu.z * hdt);
        const u64 suw = pk(uu.w * hdt, uu.w * hdt);
        PQ y; y.lo = 0ull; y.hi = 0ull;
#pragma unroll
        for (int s = 0; s < SH; s++) {
            const float4 Bq = B4[td * SQ + s0 + s];
            const float4 Cq = C4[td * SQ + s0 + s];
            const QP bp = make_perm(Bq.x, Bq.y, Bq.z, Bq.w);
            const PQ Bu0 = qmac(bp, sux, suy, suz, suw, 0ull, 0ull);

            float qx, qy, qz, qw;
            step_q_s(dtv, ah[s], qx, qy, qz, qw);
            const QP qp = make_perm(qx, qy, qz, qw);

            // h = q (x) (h + Bu0) + Bu0
            PQ X; X.lo = add2(h[s].lo, Bu0.lo); X.hi = add2(h[s].hi, Bu0.hi);
            u64 sx, sy, sz, sw; splat4(X, sx, sy, sz, sw);
            h[s] = qmac(qp, sx, sy, sz, sw, Bu0.lo, Bu0.hi);

            // y += C (x) h
            const QP cp = make_perm(Cq.x, Cq.y, Cq.z, Cq.w);
            u64 hx, hy, hz, hw; splat4(h[s], hx, hy, hz, hw);
            y = qmac(cp, hx, hy, hz, hw, y.lo, y.hi);
        }
        // Pair-reduce across s-halves (lane bit 4), packed adds.
        const u64 plo = __shfl_xor_sync(0xffffffffu, y.lo, 16);
        const u64 phi = __shfl_xor_sync(0xffffffffu, y.hi, 16);
        y.lo = add2(y.lo, plo);
        y.hi = add2(y.hi, phi);
        if (de.hbit == 0)
            o2[td * DQ + d] = make_ulonglong2(y.lo, y.hi);
    }
}

// ---------------------------------------------------------------------------
// Launch (single stream, R8 structure)
// ---------------------------------------------------------------------------
extern "C" void kernel_launch(void* const* d_in, const int* in_sizes, int n_in,
                              void* d_out, int out_size)
{
    const float* u     = (const float*)d_in[0];
    const float* dt    = (const float*)d_in[1];
    const float* Bin   = (const float*)d_in[2];
    const float* Cin   = (const float*)d_in[3];
    const float* A_log = (const float*)d_in[4];
    const float* A_i   = (const float*)d_in[5];
    const float* A_j   = (const float*)d_in[6];
    const float* A_k   = (const float*)d_in[7];
    float* out = (float*)d_out;

    const int k13_threads = BSZ * NC * DQ * 2;      // 262144
    const int k2_threads  = BSZ * SQ * DQ * 32;     // 131072 (warp per chain)

    k_summary<<<k13_threads / 256, 256>>>(u, dt, Bin, A_log, A_i, A_j, A_k);
    k_carry<<<k2_threads / 256, 256>>>();
    k_final<<<k13_threads / 256, 256>>>(u, dt, Bin, Cin, A_log, A_i, A_j, A_k, out);
}